// round 4
// baseline (speedup 1.0000x reference)
#include <cuda_runtime.h>
#include <math.h>

#define BB 2
#define NN 8192
#define KK 32
#define CC 128
#define HH 128
#define ALPHA 0.3f
#define EPS 1e-6f

__device__ float g_H[(size_t)BB * NN * HH];    // leaky(emb @ Qw + Qb), 8 MB
__device__ float g_wsh[(size_t)BB * NN * HH];  // weighted-sum hidden,  8 MB

// ---- packed fp32x2 helpers (Blackwell FFMA2; 2x fp32 throughput) ----------
__device__ __forceinline__ void ffma2(unsigned long long& acc,
                                      unsigned long long a,
                                      unsigned long long b) {
    asm("fma.rn.f32x2 %0, %1, %2, %0;" : "+l"(acc) : "l"(a), "l"(b));
}
__device__ __forceinline__ unsigned long long pack2(float lo, float hi) {
    unsigned long long r;
    asm("mov.b64 %0, {%1, %2};" : "=l"(r) : "f"(lo), "f"(hi));
    return r;
}
__device__ __forceinline__ float unpack_sum(unsigned long long v) {
    float lo, hi;
    asm("mov.b64 {%0, %1}, %2;" : "=f"(lo), "=f"(hi) : "l"(v));
    return lo + hi;
}

// ---------------------------------------------------------------------------
// K1: H[row,h] = leaky(sum_c emb[row,c]*Qw[c,h] + Qb[h])
// Block = 8 rows x 128 threads (thread t owns column h=t); grid 2048 so
// ~14 blocks/SM -> latency hidden by warp supply, not per-thread ILP alone.
// ---------------------------------------------------------------------------
__global__ void __launch_bounds__(128) k1_qgemm(const float* __restrict__ emb,
                                                const float* __restrict__ Qw,
                                                const float* __restrict__ Qb) {
    const int RB = 8;
    __shared__ float es[RB][CC];
    const int row0 = blockIdx.x * RB;
    const int t = threadIdx.x;

    // 8 rows * 128 = 1024 floats = 256 float4, 128 threads -> 2 iters
    const float4* src = (const float4*)(emb + (size_t)row0 * CC);
    float4* dst = (float4*)&es[0][0];
#pragma unroll
    for (int i = 0; i < (RB * CC / 4) / 128; i++)
        dst[t + i * 128] = src[t + i * 128];
    __syncthreads();

    unsigned long long acc[RB];
#pragma unroll
    for (int r = 0; r < RB; r++) acc[r] = 0ull;

#pragma unroll 4
    for (int c = 0; c < CC; c += 4) {
        const unsigned long long w01 = pack2(Qw[(c + 0) * HH + t], Qw[(c + 1) * HH + t]);
        const unsigned long long w23 = pack2(Qw[(c + 2) * HH + t], Qw[(c + 3) * HH + t]);
#pragma unroll
        for (int r = 0; r < RB; r++) {
            const ulonglong2 e = *(const ulonglong2*)&es[r][c];  // LDS.128 broadcast
            ffma2(acc[r], e.x, w01);
            ffma2(acc[r], e.y, w23);
        }
    }

    const float b = Qb[t];
#pragma unroll
    for (int r = 0; r < RB; r++) {
        float v = unpack_sum(acc[r]) + b;
        v = (v >= 0.f) ? v : ALPHA * v;
        g_H[(size_t)(row0 + r) * HH + t] = v;
    }
}

// ---------------------------------------------------------------------------
// K2: wsh[b,n,h] = sum_k H[b,js[k],h]*ws[k] / (sum_k ws + eps)
// One block per n, both batches. 128 threads = 32 col-groups x 4 k-groups.
// ---------------------------------------------------------------------------
__global__ void __launch_bounds__(128) k2_gather(const float* __restrict__ weights,
                                                 const int* __restrict__ ns) {
    const int n = blockIdx.x;
    const int t = threadIdx.x;
    const int c4 = t & 31;   // column group: h = 4*c4 .. 4*c4+3
    const int kg = t >> 5;   // k-group 0..3

    __shared__ float ws[KK];
    __shared__ int   js[KK];
    __shared__ float wsum_s;
    __shared__ float4 red0[4][32];
    __shared__ float4 red1[4][32];

    if (t < KK) {
        int j = ns[n * KK + t];
        js[t] = j;
        float w = weights[(size_t)n * NN + j];
        ws[t] = w;
#pragma unroll
        for (int off = 16; off; off >>= 1)
            w += __shfl_xor_sync(0xffffffffu, w, off);
        if (t == 0) wsum_s = w;
    }
    __syncthreads();

    const float* H0 = g_H;
    const float* H1 = g_H + (size_t)NN * HH;
    float4 a0 = make_float4(0.f, 0.f, 0.f, 0.f);
    float4 a1 = make_float4(0.f, 0.f, 0.f, 0.f);
#pragma unroll
    for (int k = kg; k < KK; k += 4) {
        const int j = js[k];
        const float w = ws[k];
        const float4 h0 = *(const float4*)&H0[(size_t)j * HH + 4 * c4];
        const float4 h1 = *(const float4*)&H1[(size_t)j * HH + 4 * c4];
        a0.x = fmaf(h0.x, w, a0.x); a0.y = fmaf(h0.y, w, a0.y);
        a0.z = fmaf(h0.z, w, a0.z); a0.w = fmaf(h0.w, w, a0.w);
        a1.x = fmaf(h1.x, w, a1.x); a1.y = fmaf(h1.y, w, a1.y);
        a1.z = fmaf(h1.z, w, a1.z); a1.w = fmaf(h1.w, w, a1.w);
    }
    red0[kg][c4] = a0;
    red1[kg][c4] = a1;
    __syncthreads();

    if (t < 64) {
        const int b = t >> 5;      // 0 or 1
        const int c = t & 31;
        const float4 p0 = b ? red1[0][c] : red0[0][c];
        const float4 p1 = b ? red1[1][c] : red0[1][c];
        const float4 p2 = b ? red1[2][c] : red0[2][c];
        const float4 p3 = b ? red1[3][c] : red0[3][c];
        const float inv = 1.f / (wsum_s + EPS);
        float4 o;
        o.x = (p0.x + p1.x + p2.x + p3.x) * inv;
        o.y = (p0.y + p1.y + p2.y + p3.y) * inv;
        o.z = (p0.z + p1.z + p2.z + p3.z) * inv;
        o.w = (p0.w + p1.w + p2.w + p3.w) * inv;
        *(float4*)&g_wsh[((size_t)b * NN + n) * HH + 4 * c] = o;
    }
}

// ---------------------------------------------------------------------------
// K3: out[row,h] = normalize_h( leaky( [emb_row | wsh_row] @ Ww + Wb ) )
// Block = 8 rows x 128 threads; packed-f32x2 inner loop, fused epilogue.
// ---------------------------------------------------------------------------
__global__ void __launch_bounds__(128) k3_out(const float* __restrict__ emb,
                                              const float* __restrict__ Ww,
                                              const float* __restrict__ Wb,
                                              float* __restrict__ out) {
    const int RB = 8;
    __shared__ float cs[RB][CC + HH];   // 8 KB
    __shared__ float red[RB][4];
    const int row0 = blockIdx.x * RB;
    const int t = threadIdx.x;

    // 8 rows of emb (256 float4) + 8 rows of wsh (256 float4)
    const float4* se = (const float4*)(emb   + (size_t)row0 * CC);
    const float4* sw = (const float4*)(g_wsh + (size_t)row0 * HH);
#pragma unroll
    for (int i = 0; i < (RB * CC / 4) / 128; i++) {
        int idx = t + i * 128;
        int r = idx >> 5;
        int c4 = idx & 31;
        ((float4*)&cs[r][0])[c4]  = se[idx];
        ((float4*)&cs[r][CC])[c4] = sw[idx];
    }
    __syncthreads();

    unsigned long long acc[RB];
#pragma unroll
    for (int r = 0; r < RB; r++) acc[r] = 0ull;

#pragma unroll 4
    for (int f = 0; f < CC + HH; f += 4) {
        const unsigned long long w01 = pack2(Ww[(f + 0) * HH + t], Ww[(f + 1) * HH + t]);
        const unsigned long long w23 = pack2(Ww[(f + 2) * HH + t], Ww[(f + 3) * HH + t]);
#pragma unroll
        for (int r = 0; r < RB; r++) {
            const ulonglong2 e = *(const ulonglong2*)&cs[r][f];  // LDS.128
            ffma2(acc[r], e.x, w01);
            ffma2(acc[r], e.y, w23);
        }
    }

    const float b = Wb[t];
    const int warp = t >> 5, lane = t & 31;
    float vals[RB];
#pragma unroll
    for (int r = 0; r < RB; r++) {
        float v = unpack_sum(acc[r]) + b;
        v = (v >= 0.f) ? v : ALPHA * v;
        vals[r] = v;
        float s = v * v;
#pragma unroll
        for (int off = 16; off; off >>= 1)
            s += __shfl_xor_sync(0xffffffffu, s, off);
        if (lane == 0) red[r][warp] = s;
    }
    __syncthreads();

#pragma unroll
    for (int r = 0; r < RB; r++) {
        float nrm = sqrtf(red[r][0] + red[r][1] + red[r][2] + red[r][3]);
        out[(size_t)(row0 + r) * HH + t] = vals[r] / (nrm + EPS);
    }
}

// ---------------------------------------------------------------------------
extern "C" void kernel_launch(void* const* d_in, const int* in_sizes, int n_in,
                              void* d_out, int out_size) {
    const float* emb     = (const float*)d_in[0];  // (B, N, C)
    const float* weights = (const float*)d_in[1];  // (N, N)
    const int*   ns      = (const int*)  d_in[2];  // (N, K)
    const float* Qw      = (const float*)d_in[3];  // (C, H)
    const float* Qb      = (const float*)d_in[4];  // (H,)
    const float* Ww      = (const float*)d_in[5];  // (C+H, H)
    const float* Wb      = (const float*)d_in[6];  // (H,)
    float* out = (float*)d_out;                    // (B, N, H)

    (void)in_sizes; (void)n_in; (void)out_size;

    k1_qgemm<<<(BB * NN) / 8, 128>>>(emb, Qw, Qb);
    k2_gather<<<NN, 128>>>(weights, ns);
    k3_out<<<(BB * NN) / 8, 128>>>(emb, Ww, Wb, out);
}

// round 6
// speedup vs baseline: 1.2834x; 1.2834x over previous
#include <cuda_runtime.h>
#include <math.h>

#define BB 2
#define NN 8192
#define KK 32
#define CC 128
#define HH 128
#define ALPHA 0.3f
#define EPS 1e-6f

#define RT 64            // rows per block tile
#define AS_STRIDE 66     // padded floats per As k-row (264B: 8B-aligned, conflict-spread)
#define SMEM_FLOATS (128 * AS_STRIDE + 128 * HH)
#define SMEM_BYTES (SMEM_FLOATS * 4)

__device__ float g_H[(size_t)BB * NN * HH];    // leaky(emb @ Qw + Qb), 8 MB
__device__ float g_wsh[(size_t)BB * NN * HH];  // weighted-sum hidden,  8 MB

// ---- packed fp32x2 helpers -------------------------------------------------
__device__ __forceinline__ void ffma2(unsigned long long& acc,
                                      unsigned long long a,
                                      unsigned long long b) {
    asm("fma.rn.f32x2 %0, %1, %2, %0;" : "+l"(acc) : "l"(a), "l"(b));
}
__device__ __forceinline__ unsigned long long pack_dup(float v) {
    unsigned long long r;
    asm("mov.b64 %0, {%1, %1};" : "=l"(r) : "f"(v));
    return r;
}
__device__ __forceinline__ void unpack2(unsigned long long v, float& lo, float& hi) {
    asm("mov.b64 {%0, %1}, %2;" : "=f"(lo), "=f"(hi) : "l"(v));
}
__device__ __forceinline__ float leaky(float v) {
    return (v >= 0.f) ? v : ALPHA * v;
}

// ---- shared-memory stagers -------------------------------------------------
// A: 64 rows x 128 cols row-major -> As[k][row] transposed (stride AS_STRIDE)
__device__ __forceinline__ void load_A_transposed(float* __restrict__ As,
                                                  const float* __restrict__ src,
                                                  int t) {
    const float4* s4 = (const float4*)src;
#pragma unroll
    for (int i = 0; i < 16; i++) {
        int idx = t + i * 128;
        int row = idx >> 5;          // 0..63
        int c = (idx & 31) << 2;     // 0,4,..124
        float4 v = s4[idx];
        As[(c + 0) * AS_STRIDE + row] = v.x;
        As[(c + 1) * AS_STRIDE + row] = v.y;
        As[(c + 2) * AS_STRIDE + row] = v.z;
        As[(c + 3) * AS_STRIDE + row] = v.w;
    }
}
// B: 128 x 128 weights, direct copy
__device__ __forceinline__ void load_B(float* __restrict__ Bs,
                                       const float* __restrict__ W, int t) {
    const float4* w4 = (const float4*)W;
    float4* b4 = (float4*)Bs;
#pragma unroll
    for (int i = 0; i < 32; i++) b4[t + i * 128] = w4[t + i * 128];
}

// ---- 8x8 register-tile mainloop over K=128 --------------------------------
// acc[i2][j]: f32x2 lanes = rows (tr*8+2*i2, tr*8+2*i2+1), col = tc*8+j
__device__ __forceinline__ void gemm_128(const float* __restrict__ As,
                                         const float* __restrict__ Bs,
                                         int tr, int tc,
                                         unsigned long long acc[4][8]) {
#pragma unroll 4
    for (int k = 0; k < 128; k++) {
        const unsigned long long* ap =
            (const unsigned long long*)(As + k * AS_STRIDE + tr * 8);
        unsigned long long av[4];
        av[0] = ap[0]; av[1] = ap[1]; av[2] = ap[2]; av[3] = ap[3];
        const float4 bl = *(const float4*)(Bs + k * HH + tc * 8);
        const float4 bh = *(const float4*)(Bs + k * HH + tc * 8 + 4);
        unsigned long long bv[8];
        bv[0] = pack_dup(bl.x); bv[1] = pack_dup(bl.y);
        bv[2] = pack_dup(bl.z); bv[3] = pack_dup(bl.w);
        bv[4] = pack_dup(bh.x); bv[5] = pack_dup(bh.y);
        bv[6] = pack_dup(bh.z); bv[7] = pack_dup(bh.w);
#pragma unroll
        for (int i = 0; i < 4; i++)
#pragma unroll
            for (int j = 0; j < 8; j++)
                ffma2(acc[i][j], av[i], bv[j]);
    }
}

// ---------------------------------------------------------------------------
// K1: H[row,h] = leaky(emb[row,:] @ Qw + Qb)
// ---------------------------------------------------------------------------
__global__ void __launch_bounds__(128) k1_qgemm(const float* __restrict__ emb,
                                                const float* __restrict__ Qw,
                                                const float* __restrict__ Qb) {
    extern __shared__ float sm[];
    float* As = sm;
    float* Bs = sm + 128 * AS_STRIDE;
    const int t = threadIdx.x;
    const int tr = t >> 4, tc = t & 15;
    const int row0 = blockIdx.x * RT;

    load_B(Bs, Qw, t);
    load_A_transposed(As, emb + (size_t)row0 * CC, t);
    __syncthreads();

    unsigned long long acc[4][8];
#pragma unroll
    for (int i = 0; i < 4; i++)
#pragma unroll
        for (int j = 0; j < 8; j++) acc[i][j] = 0ull;

    gemm_128(As, Bs, tr, tc, acc);

    float bias[8];
    *(float4*)&bias[0] = *(const float4*)(Qb + tc * 8);
    *(float4*)&bias[4] = *(const float4*)(Qb + tc * 8 + 4);

#pragma unroll
    for (int i2 = 0; i2 < 4; i2++) {
        float r0[8], r1[8];
#pragma unroll
        for (int j = 0; j < 8; j++) {
            unpack2(acc[i2][j], r0[j], r1[j]);
            r0[j] = leaky(r0[j] + bias[j]);
            r1[j] = leaky(r1[j] + bias[j]);
        }
        float* o0 = g_H + (size_t)(row0 + tr * 8 + 2 * i2) * HH + tc * 8;
        float* o1 = o0 + HH;
        *(float4*)o0 = make_float4(r0[0], r0[1], r0[2], r0[3]);
        *(float4*)(o0 + 4) = make_float4(r0[4], r0[5], r0[6], r0[7]);
        *(float4*)o1 = make_float4(r1[0], r1[1], r1[2], r1[3]);
        *(float4*)(o1 + 4) = make_float4(r1[4], r1[5], r1[6], r1[7]);
    }
}

// ---------------------------------------------------------------------------
// K2: wsh[b,n,h] = sum_k H[b,js[k],h]*ws[k] / (sum_k ws + eps)
// ---------------------------------------------------------------------------
__global__ void __launch_bounds__(128) k2_gather(const float* __restrict__ weights,
                                                 const int* __restrict__ ns) {
    const int n = blockIdx.x;
    const int t = threadIdx.x;
    const int c4 = t & 31;
    const int kg = t >> 5;

    __shared__ float ws[KK];
    __shared__ int   js[KK];
    __shared__ float wsum_s;
    __shared__ float4 red0[4][32];
    __shared__ float4 red1[4][32];

    if (t < KK) {
        int j = ns[n * KK + t];
        js[t] = j;
        float w = weights[(size_t)n * NN + j];
        ws[t] = w;
#pragma unroll
        for (int off = 16; off; off >>= 1)
            w += __shfl_xor_sync(0xffffffffu, w, off);
        if (t == 0) wsum_s = w;
    }
    __syncthreads();

    const float* H0 = g_H;
    const float* H1 = g_H + (size_t)NN * HH;
    float4 a0 = make_float4(0.f, 0.f, 0.f, 0.f);
    float4 a1 = make_float4(0.f, 0.f, 0.f, 0.f);
#pragma unroll
    for (int k = kg; k < KK; k += 4) {
        const int j = js[k];
        const float w = ws[k];
        const float4 h0 = *(const float4*)&H0[(size_t)j * HH + 4 * c4];
        const float4 h1 = *(const float4*)&H1[(size_t)j * HH + 4 * c4];
        a0.x = fmaf(h0.x, w, a0.x); a0.y = fmaf(h0.y, w, a0.y);
        a0.z = fmaf(h0.z, w, a0.z); a0.w = fmaf(h0.w, w, a0.w);
        a1.x = fmaf(h1.x, w, a1.x); a1.y = fmaf(h1.y, w, a1.y);
        a1.z = fmaf(h1.z, w, a1.z); a1.w = fmaf(h1.w, w, a1.w);
    }
    red0[kg][c4] = a0;
    red1[kg][c4] = a1;
    __syncthreads();

    if (t < 64) {
        const int b = t >> 5;
        const int c = t & 31;
        const float4 p0 = b ? red1[0][c] : red0[0][c];
        const float4 p1 = b ? red1[1][c] : red0[1][c];
        const float4 p2 = b ? red1[2][c] : red0[2][c];
        const float4 p3 = b ? red1[3][c] : red0[3][c];
        const float inv = 1.f / (wsum_s + EPS);
        float4 o;
        o.x = (p0.x + p1.x + p2.x + p3.x) * inv;
        o.y = (p0.y + p1.y + p2.y + p3.y) * inv;
        o.z = (p0.z + p1.z + p2.z + p3.z) * inv;
        o.w = (p0.w + p1.w + p2.w + p3.w) * inv;
        *(float4*)&g_wsh[((size_t)b * NN + n) * HH + 4 * c] = o;
    }
}

// ---------------------------------------------------------------------------
// K3: out = normalize(leaky([emb | wsh] @ Ww + Wb)), K=256 as two K=128 halves
// ---------------------------------------------------------------------------
__global__ void __launch_bounds__(128) k3_out(const float* __restrict__ emb,
                                              const float* __restrict__ Ww,
                                              const float* __restrict__ Wb,
                                              float* __restrict__ out) {
    extern __shared__ float sm[];
    float* As = sm;
    float* Bs = sm + 128 * AS_STRIDE;
    const int t = threadIdx.x;
    const int tr = t >> 4, tc = t & 15;
    const int row0 = blockIdx.x * RT;

    unsigned long long acc[4][8];
#pragma unroll
    for (int i = 0; i < 4; i++)
#pragma unroll
        for (int j = 0; j < 8; j++) acc[i][j] = 0ull;

    // half 0: A = emb rows, B = Ww[0:128,:]
    load_B(Bs, Ww, t);
    load_A_transposed(As, emb + (size_t)row0 * CC, t);
    __syncthreads();
    gemm_128(As, Bs, tr, tc, acc);
    __syncthreads();

    // half 1: A = wsh rows, B = Ww[128:256,:]
    load_B(Bs, Ww + 128 * HH, t);
    load_A_transposed(As, g_wsh + (size_t)row0 * HH, t);
    __syncthreads();
    gemm_128(As, Bs, tr, tc, acc);

    float bias[8];
    *(float4*)&bias[0] = *(const float4*)(Wb + tc * 8);
    *(float4*)&bias[4] = *(const float4*)(Wb + tc * 8 + 4);

    float v[8][8];
    float ssq[8];
#pragma unroll
    for (int i2 = 0; i2 < 4; i2++) {
#pragma unroll
        for (int j = 0; j < 8; j++) {
            float lo, hi;
            unpack2(acc[i2][j], lo, hi);
            v[2 * i2][j]     = leaky(lo + bias[j]);
            v[2 * i2 + 1][j] = leaky(hi + bias[j]);
        }
    }
#pragma unroll
    for (int i = 0; i < 8; i++) {
        float s = 0.f;
#pragma unroll
        for (int j = 0; j < 8; j++) s = fmaf(v[i][j], v[i][j], s);
        // reduce across the 16 tc-threads (lane bits 0..3)
#pragma unroll
        for (int off = 8; off; off >>= 1)
            s += __shfl_xor_sync(0xffffffffu, s, off);
        ssq[i] = s;
    }
#pragma unroll
    for (int i = 0; i < 8; i++) {
        const float inv = 1.f / (sqrtf(ssq[i]) + EPS);
        float* o = out + (size_t)(row0 + tr * 8 + i) * HH + tc * 8;
        *(float4*)o = make_float4(v[i][0] * inv, v[i][1] * inv,
                                  v[i][2] * inv, v[i][3] * inv);
        *(float4*)(o + 4) = make_float4(v[i][4] * inv, v[i][5] * inv,
                                        v[i][6] * inv, v[i][7] * inv);
    }
}

// ---------------------------------------------------------------------------
extern "C" void kernel_launch(void* const* d_in, const int* in_sizes, int n_in,
                              void* d_out, int out_size) {
    const float* emb     = (const float*)d_in[0];  // (B, N, C)
    const float* weights = (const float*)d_in[1];  // (N, N)
    const int*   ns      = (const int*)  d_in[2];  // (N, K)
    const float* Qw      = (const float*)d_in[3];  // (C, H)
    const float* Qb      = (const float*)d_in[4];  // (H,)
    const float* Ww      = (const float*)d_in[5];  // (C+H, H)
    const float* Wb      = (const float*)d_in[6];  // (H,)
    float* out = (float*)d_out;                    // (B, N, H)

    (void)in_sizes; (void)n_in; (void)out_size;

    cudaFuncSetAttribute(k1_qgemm, cudaFuncAttributeMaxDynamicSharedMemorySize,
                         SMEM_BYTES);
    cudaFuncSetAttribute(k3_out, cudaFuncAttributeMaxDynamicSharedMemorySize,
                         SMEM_BYTES);

    k1_qgemm<<<(BB * NN) / RT, 128, SMEM_BYTES>>>(emb, Qw, Qb);
    k2_gather<<<NN, 128>>>(weights, ns);
    k3_out<<<(BB * NN) / RT, 128, SMEM_BYTES>>>(emb, Ww, Wb, out);
}